// round 5
// baseline (speedup 1.0000x reference)
#include <cuda_runtime.h>

#define BB 8
#define HH 512
#define WW 512
#define NN 128
#define HWSZ (HH*WW)
#define TXW 64                 // tile width
#define TYH 32                 // tile height
#define NTX (WW/TXW)           // 8 tiles across
#define NTY (HH/TYH)           // 16 tiles down
#define NBLK (BB*NTX*NTY)      // 1024 blocks

// ---- scratch (no allocations allowed) ----
__device__ float g_psm[NBLK], g_phm[NBLK];
__device__ unsigned int g_done = 0;

// One block per 64x32 tile. 256 threads; each thread owns one float4 in each
// of 2 rows (y0+ty, y0+ty+16) = 8 pixels. float4 loads; float2 gt stores
// (gt base = out+2 is only 8-byte aligned).
__global__ void __launch_bounds__(256, 4) k_fused(const float* __restrict__ hm,
                                                  const float* __restrict__ sm,
                                                  const float* __restrict__ mask,
                                                  const float* __restrict__ gr,
                                                  const int*   __restrict__ centers,
                                                  float* __restrict__ out) {
    __shared__ float scy[NN], scx[NN], sinv[NN];
    __shared__ int   scnt;
    __shared__ float red0[8], red1[8];
    __shared__ int   s_last;

    int blk = blockIdx.x;
    int b   = blk >> 7;            // 128 tiles per sample
    int t   = blk & 127;
    int y0  = (t >> 3) * TYH;      // 16 y-tiles
    int x0  = (t & 7)  * TXW;      // 8 x-tiles
    int tid = threadIdx.x;
    int tx  = tid & 15;            // x-group (4 px each): 16 groups * 4 = 64 wide
    int ty  = tid >> 4;            // 16 rows; thread covers ty and ty+16

    if (tid == 0) scnt = 0;
    __syncthreads();

    int x = x0 + tx * 4;
    long e0 = (long)b * HWSZ + (long)(y0 + ty) * WW + x;
    long e1 = e0 + 16L * WW;

    const float4* sm4 = (const float4*)sm;
    const float4* hm4 = (const float4*)hm;
    const float4* mk4 = (const float4*)mask;
    float* gt = out + 2;

    // Prefetch sm rows (independent of centers) — overlaps sigma gather latency.
    float4 s0 = sm4[e0 >> 2], s1 = sm4[e1 >> 2];

    // Per-center sigma + cull (threads 0..127): fp32 exp(-q)==0 for q>~103.
    if (tid < NN) {
        int cyi = centers[(b*NN + tid)*2 + 0]; cyi = min(max(cyi, 0), HH - 1);
        int cxi = centers[(b*NN + tid)*2 + 1]; cxi = min(max(cxi, 0), WW - 1);
        float s   = __ldg(&sm[b*HWSZ + cyi*WW + cxi]);
        float grb = __ldg(&gr[b]);
        float sigma = 0.2f/grb + fmaxf(s, 0.0f) * 0.2f / grb;  // PR_MIN/gr + relu*RES/gr
        float inv = 1.0f / (2.0f * sigma * sigma);
        float cy = (float)cyi, cx = (float)cxi;
        float ddy = fmaxf(fmaxf((float)y0 - cy, cy - (float)(y0 + TYH - 1)), 0.0f);
        float ddx = fmaxf(fmaxf((float)x0 - cx, cx - (float)(x0 + TXW - 1)), 0.0f);
        float qmin = (ddy*ddy + ddx*ddx) * inv;
        if (qmin < 104.0f) {
            int p = atomicAdd(&scnt, 1);  // order irrelevant: fminf exact & commutative
            scy[p] = cy; scx[p] = cx; sinv[p] = inv;
        }
    }

    // sm^2 partial while the gather chain drains.
    float lsm = 0.0f;
    lsm = fmaf(s0.x,s0.x, fmaf(s0.y,s0.y, fmaf(s0.z,s0.z, fmaf(s0.w,s0.w, lsm))));
    lsm = fmaf(s1.x,s1.x, fmaf(s1.y,s1.y, fmaf(s1.z,s1.z, fmaf(s1.w,s1.w, lsm))));

    __syncthreads();
    int cnt = scnt;

    // Prefetch hm/mask (streaming) so they drain under the compute loop.
    float4 h0 = __ldcg(&hm4[e0 >> 2]);
    float4 h1 = __ldcg(&hm4[e1 >> 2]);
    float4 m0 = __ldcg(&mk4[e0 >> 2]);
    float4 m1 = __ldcg(&mk4[e1 >> 2]);

    float xf  = (float)x;
    float yf0 = (float)(y0 + ty);
    float yf1 = yf0 + 16.0f;

    float q0[4], q1[4];
    #pragma unroll
    for (int j = 0; j < 4; j++) { q0[j] = 1e30f; q1[j] = 1e30f; }

    for (int k = 0; k < cnt; k++) {
        float cxk = scx[k], cyk = scy[k], inv = sinv[k];
        float ax[4];
        #pragma unroll
        for (int j = 0; j < 4; j++) {
            float dx = xf + (float)j - cxk;
            ax[j] = dx * dx * inv;
        }
        float d0 = yf0 - cyk, d1 = yf1 - cyk;
        float by0 = d0 * d0 * inv;
        float by1 = d1 * d1 * inv;
        #pragma unroll
        for (int j = 0; j < 4; j++) {
            q0[j] = fminf(q0[j], ax[j] + by0);
            q1[j] = fminf(q1[j], ax[j] + by1);
        }
    }

    // gt + hm loss (exp underflows to exact 0 for far pixels, matching ref).
    float g00 = __expf(-q0[0]), g01 = __expf(-q0[1]), g02 = __expf(-q0[2]), g03 = __expf(-q0[3]);
    float g10 = __expf(-q1[0]), g11 = __expf(-q1[1]), g12 = __expf(-q1[2]), g13 = __expf(-q1[3]);
    *(float2*)(gt + e0)     = make_float2(g00, g01);
    *(float2*)(gt + e0 + 2) = make_float2(g02, g03);
    *(float2*)(gt + e1)     = make_float2(g10, g11);
    *(float2*)(gt + e1 + 2) = make_float2(g12, g13);

    float lhm = 0.0f;
    float d;
    d = h0.x - g00; lhm = fmaf(d*d, m0.x, lhm);
    d = h0.y - g01; lhm = fmaf(d*d, m0.y, lhm);
    d = h0.z - g02; lhm = fmaf(d*d, m0.z, lhm);
    d = h0.w - g03; lhm = fmaf(d*d, m0.w, lhm);
    d = h1.x - g10; lhm = fmaf(d*d, m1.x, lhm);
    d = h1.y - g11; lhm = fmaf(d*d, m1.y, lhm);
    d = h1.z - g12; lhm = fmaf(d*d, m1.z, lhm);
    d = h1.w - g13; lhm = fmaf(d*d, m1.w, lhm);

    // Deterministic block reduction (fixed tree order).
    #pragma unroll
    for (int o = 16; o; o >>= 1) {
        lsm += __shfl_down_sync(0xffffffffu, lsm, o);
        lhm += __shfl_down_sync(0xffffffffu, lhm, o);
    }
    int wid = tid >> 5, lane = tid & 31;
    if (lane == 0) { red0[wid] = lsm; red1[wid] = lhm; }
    __syncthreads();
    if (tid == 0) {
        float a = 0.0f, c = 0.0f;
        #pragma unroll
        for (int i = 0; i < 8; i++) { a += red0[i]; c += red1[i]; }
        g_psm[blk] = a;
        g_phm[blk] = c;
        __threadfence();
        unsigned v = atomicAdd(&g_done, 1u);
        s_last = (v == (unsigned)(NBLK - 1)) ? 1 : 0;
    }
    __syncthreads();

    // Last block: final reduction (fixed order, deterministic).
    if (s_last) {
        float a = 0.0f, c = 0.0f;
        for (int i = tid; i < NBLK; i += 256) {
            a += __ldcg(&g_psm[i]);
            c += __ldcg(&g_phm[i]);
        }
        #pragma unroll
        for (int o = 16; o; o >>= 1) {
            a += __shfl_down_sync(0xffffffffu, a, o);
            c += __shfl_down_sync(0xffffffffu, c, o);
        }
        if (lane == 0) { red0[wid] = a; red1[wid] = c; }
        __syncthreads();
        if (tid == 0) {
            float sa = 0.0f, sc = 0.0f;
            #pragma unroll
            for (int i = 0; i < 8; i++) { sa += red0[i]; sc += red1[i]; }
            out[0] = sa / (float)((long)BB * HWSZ);   // mean of per-sample mean(sm^2)
            out[1] = sc / (float)((long)BB * HWSZ);   // mean of per-sample masked MSE
            g_done = 0;   // reset for next graph replay
        }
    }
}

extern "C" void kernel_launch(void* const* d_in, const int* in_sizes, int n_in,
                              void* d_out, int out_size) {
    const float* hm      = (const float*)d_in[0];
    const float* sm      = (const float*)d_in[1];
    const float* gr      = (const float*)d_in[2];
    const float* mask    = (const float*)d_in[3];
    const int*   centers = (const int*)d_in[4];
    float* out = (float*)d_out;

    k_fused<<<NBLK, 256>>>(hm, sm, mask, gr, centers, out);
}